// round 3
// baseline (speedup 1.0000x reference)
#include <cuda_runtime.h>
#include <cstddef>

typedef unsigned long long ull;

#define NTHREADS 256
#define TROWS 64

// ======================= duplicated-weight scratch buffer =======================
// Every weight w is stored as adjacent pair (w,w) so it can be used directly as
// the broadcast operand of fma.rn.f32x2. Biases likewise.
#define DUP_FLOATS 132480
__device__ __align__(16) float g_wdup[DUP_FLOATS];

// weight segments (src sizes): h1/h2/h3 4096, b1/b2/b3 6400, c1 20736, c2 9216, c3 4096
__constant__ int c_wpre[10] = {0,4096,8192,12288,18688,25088,31488,52224,61440,65536};
__constant__ int c_wdst[9]  = {0,8192,16384,24576,37376,50176,62976,104448,122880};
// bias segments: 64,64,64,80,80,80,144,64,64
__constant__ int c_bpre[10] = {0,64,128,192,272,352,432,576,640,704};
__constant__ int c_bdst[9]  = {131072,131200,131328,131456,131616,131776,131936,132224,132352};

__global__ void dup_kernel(const float* w0,const float* w1,const float* w2,
                           const float* w3,const float* w4,const float* w5,
                           const float* w6,const float* w7,const float* w8,
                           const float* b0,const float* b1,const float* b2,
                           const float* b3,const float* b4,const float* b5,
                           const float* b6,const float* b7,const float* b8)
{
    const float* W[9] = {w0,w1,w2,w3,w4,w5,w6,w7,w8};
    const float* Bv[9] = {b0,b1,b2,b3,b4,b5,b6,b7,b8};
    int i = blockIdx.x * blockDim.x + threadIdx.x;
    if (i < 65536) {
        int s = 0;
        while (i >= c_wpre[s + 1]) s++;
        int l = i - c_wpre[s];
        float v = W[s][l];
        g_wdup[c_wdst[s] + 2 * l]     = v;
        g_wdup[c_wdst[s] + 2 * l + 1] = v;
    } else if (i < 66240) {
        int j = i - 65536;
        int s = 0;
        while (j >= c_bpre[s + 1]) s++;
        int l = j - c_bpre[s];
        float v = Bv[s][l];
        g_wdup[c_bdst[s] + 2 * l]     = v;
        g_wdup[c_bdst[s] + 2 * l + 1] = v;
    }
}

// ======================= packed fp32x2 helpers =======================
__device__ __forceinline__ ull ffma2(ull a, ull b, ull c) {
    ull d;
    asm("fma.rn.f32x2 %0, %1, %2, %3;" : "=l"(d) : "l"(a), "l"(b), "l"(c));
    return d;
}
__device__ __forceinline__ ull addf2(ull a, ull b) {
    ull d;
    asm("add.rn.f32x2 %0, %1, %2;" : "=l"(d) : "l"(a), "l"(b));
    return d;
}
union U2 { ull u; float2 f; };
__device__ __forceinline__ float2 asf2(ull a) { U2 u; u.u = a; return u.f; }
__device__ __forceinline__ float lrelu(float v) { return v > 0.0f ? v : 0.01f * v; }

// ======================= epilogue chunk maps =======================
__constant__ int c_kind[31] = {0,0,0,0,0,0,0,0,0,0,0,0,1,1,1,1,0,0,0,1,0,0,0,0,0,1,1,1,1,1,1};
__constant__ int c_A[31]    = {320,152,304,304,304,304,304,152,152,152,152,152,
                               40,41,42,43, 152,208,416, 39, 208,152,416,360,152,
                               44,45,46,47,48,49};
__constant__ int c_B[31]    = {18,20,22,23,24,25,26,27,28,29,30,31,
                               0,2,3,5, 35,36,37, 1, 32,33,34,19,38,
                               4,4,4,4,4,4};
// blob: suit@0(40) rank@40(112) pos@152(56) action@208(96) active@304(16)
//       street@320(40) numpl@360(56) blind@416(16)

// shared layout (floats)
#define OFF_SS    0                    // 64*52
#define OFF_BLOB  (OFF_SS + 64*52)     // 432
#define OFF_SW    (OFF_BLOB + 432)     // 48
#define OFF_SB    (OFF_SW + 48)        // 48
#define OFF_S1    (OFF_SB + 48)        // 3856 (16B aligned)
#define OFF_S2    (OFF_S1 + 144*64)    // 13072
#define SMEM_FLOATS (OFF_S2 + 144*64)  // 22288
#define SMEM_BYTES  (SMEM_FLOATS * 4)  // 89152 B -> 2 CTAs/SM

// One dense layer, 64-row tile. Xs/[NIN][64] -> Ys/[NOUT][64].
// Thread: 4 rows (2 packed pairs) x 4 cols; inner loop is pure FFMA2.
template<int NIN, int NOUT, bool ACT>
__device__ __forceinline__ void mlp_layer2(const float* __restrict__ Xs,
                                           float* __restrict__ Ys,
                                           int wdoff, int bdoff)
{
    const float* __restrict__ Wd = g_wdup + wdoff;
    const float* __restrict__ bd = g_wdup + bdoff;
    const int t = threadIdx.x;
    const int rq = (t & 15) << 2;
    const int jgrp = t >> 4;

    for (int jb = jgrp * 4; jb < NOUT; jb += 64) {
        ull acc[4][2] = {};
        const float* wp = Wd + 2 * jb;
        #pragma unroll 8
        for (int k = 0; k < NIN; k++) {
            ulonglong2 xv = *reinterpret_cast<const ulonglong2*>(Xs + (k << 6) + rq);
            ulonglong2 wa = *reinterpret_cast<const ulonglong2*>(wp);
            ulonglong2 wb = *reinterpret_cast<const ulonglong2*>(wp + 4);
            wp += 2 * NOUT;
            acc[0][0] = ffma2(xv.x, wa.x, acc[0][0]);
            acc[0][1] = ffma2(xv.y, wa.x, acc[0][1]);
            acc[1][0] = ffma2(xv.x, wa.y, acc[1][0]);
            acc[1][1] = ffma2(xv.y, wa.y, acc[1][1]);
            acc[2][0] = ffma2(xv.x, wb.x, acc[2][0]);
            acc[2][1] = ffma2(xv.y, wb.x, acc[2][1]);
            acc[3][0] = ffma2(xv.x, wb.y, acc[3][0]);
            acc[3][1] = ffma2(xv.y, wb.y, acc[3][1]);
        }
        ulonglong2 bv = *reinterpret_cast<const ulonglong2*>(bd + 2 * jb);
        ulonglong2 bw = *reinterpret_cast<const ulonglong2*>(bd + 2 * jb + 4);
        ull bj[4] = {bv.x, bv.y, bw.x, bw.y};
        #pragma unroll
        for (int jj = 0; jj < 4; jj++) {
            ull a0 = addf2(acc[jj][0], bj[jj]);
            ull a1 = addf2(acc[jj][1], bj[jj]);
            float2 lo = asf2(a0), hi = asf2(a1);
            float4 o = {lo.x, lo.y, hi.x, hi.y};
            if (ACT) { o.x = lrelu(o.x); o.y = lrelu(o.y); o.z = lrelu(o.z); o.w = lrelu(o.w); }
            *reinterpret_cast<float4*>(Ys + (jb + jj) * TROWS + rq) = o;
        }
    }
    __syncthreads();
}

// Final 64->64 layer (no activation) writing straight to out cols [0,64)
__device__ __forceinline__ void mlp_final2(const float* __restrict__ Xs,
                                           float* __restrict__ out, size_t g0,
                                           int wdoff, int bdoff)
{
    const float* __restrict__ Wd = g_wdup + wdoff;
    const float* __restrict__ bd = g_wdup + bdoff;
    const int t = threadIdx.x;
    const int rq = (t & 15) << 2;
    const int jb = (t >> 4) << 2;

    ull acc[4][2] = {};
    const float* wp = Wd + 2 * jb;
    #pragma unroll 8
    for (int k = 0; k < 64; k++) {
        ulonglong2 xv = *reinterpret_cast<const ulonglong2*>(Xs + (k << 6) + rq);
        ulonglong2 wa = *reinterpret_cast<const ulonglong2*>(wp);
        ulonglong2 wb = *reinterpret_cast<const ulonglong2*>(wp + 4);
        wp += 128;
        acc[0][0] = ffma2(xv.x, wa.x, acc[0][0]);
        acc[0][1] = ffma2(xv.y, wa.x, acc[0][1]);
        acc[1][0] = ffma2(xv.x, wa.y, acc[1][0]);
        acc[1][1] = ffma2(xv.y, wa.y, acc[1][1]);
        acc[2][0] = ffma2(xv.x, wb.x, acc[2][0]);
        acc[2][1] = ffma2(xv.y, wb.x, acc[2][1]);
        acc[3][0] = ffma2(xv.x, wb.y, acc[3][0]);
        acc[3][1] = ffma2(xv.y, wb.y, acc[3][1]);
    }
    ulonglong2 bv = *reinterpret_cast<const ulonglong2*>(bd + 2 * jb);
    ulonglong2 bw = *reinterpret_cast<const ulonglong2*>(bd + 2 * jb + 4);
    ull bj[4] = {bv.x, bv.y, bw.x, bw.y};
    float col[4][4]; // [jj][rr]
    #pragma unroll
    for (int jj = 0; jj < 4; jj++) {
        float2 lo = asf2(addf2(acc[jj][0], bj[jj]));
        float2 hi = asf2(addf2(acc[jj][1], bj[jj]));
        col[jj][0] = lo.x; col[jj][1] = lo.y; col[jj][2] = hi.x; col[jj][3] = hi.y;
    }
    #pragma unroll
    for (int rr = 0; rr < 4; rr++) {
        float4 o = {col[0][rr], col[1][rr], col[2][rr], col[3][rr]};
        *reinterpret_cast<float4*>(out + (g0 + rq + rr) * 312 + jb) = o;
    }
}

__global__ void __launch_bounds__(NTHREADS, 2)
preproc_kernel(const float* __restrict__ state,
               const float* __restrict__ suit_emb, const float* __restrict__ rank_emb,
               const float* __restrict__ pos_emb, const float* __restrict__ action_emb,
               const float* __restrict__ active_emb, const float* __restrict__ street_emb,
               const float* __restrict__ numpl_emb, const float* __restrict__ blind_emb,
               const float* __restrict__ scalar_W, const float* __restrict__ scalar_b,
               float* __restrict__ out)
{
    extern __shared__ float smem[];
    float* Ss   = smem + OFF_SS;
    float* blob = smem + OFF_BLOB;
    float* sW   = smem + OFF_SW;
    float* sB   = smem + OFF_SB;
    float* S1   = smem + OFF_S1;
    float* S2   = smem + OFF_S2;

    const int t = threadIdx.x;
    const size_t g0 = (size_t)blockIdx.x * TROWS;

    // ---- load state tile (64 rows x 50 cols, stride 52) ----
    const float* sp = state + g0 * 50;
    for (int i = t; i < TROWS * 50; i += NTHREADS) {
        int r = i / 50, c = i - r * 50;
        Ss[r * 52 + c] = sp[i];
    }
    // ---- embedding tables ----
    for (int i = t; i < 40;  i += NTHREADS) blob[0   + i] = suit_emb[i];
    for (int i = t; i < 112; i += NTHREADS) blob[40  + i] = rank_emb[i];
    for (int i = t; i < 56;  i += NTHREADS) blob[152 + i] = pos_emb[i];
    for (int i = t; i < 96;  i += NTHREADS) blob[208 + i] = action_emb[i];
    for (int i = t; i < 16;  i += NTHREADS) blob[304 + i] = active_emb[i];
    for (int i = t; i < 40;  i += NTHREADS) blob[320 + i] = street_emb[i];
    for (int i = t; i < 56;  i += NTHREADS) blob[360 + i] = numpl_emb[i];
    for (int i = t; i < 16;  i += NTHREADS) blob[416 + i] = blind_emb[i];
    for (int i = t; i < 48;  i += NTHREADS) { sW[i] = scalar_W[i]; sB[i] = scalar_b[i]; }
    __syncthreads();

    // ---- cheap output columns 64..311 ----
    for (int i = t; i < TROWS * 248; i += NTHREADS) {
        int r = i / 248, cc = i - r * 248;
        int ch = cc >> 3, e = cc & 7;
        int kind = c_kind[ch], A = c_A[ch], Bc = c_B[ch];
        float v;
        if (kind == 0) {
            int xi = (int)Ss[r * 52 + Bc];
            v = blob[A + xi * 8 + e];
        } else {
            v = Ss[r * 52 + A] * sW[Bc * 8 + e] + sB[Bc * 8 + e];
        }
        out[(g0 + r) * 312 + 64 + cc] = v;
    }

    // ---- gather hand input (64 feats) into S1 [k][row] ----
    for (int i = t; i < 64 * TROWS; i += NTHREADS) {
        int r = i & 63, k = i >> 6;
        int c = k >> 4, w = k & 15;
        float v;
        if (w < 8) { int s  = (int)Ss[r * 52 + 2 * c + 1]; v = blob[0  + s * 8 + w]; }
        else       { int rk = (int)Ss[r * 52 + 2 * c];     v = blob[40 + rk * 8 + (w - 8)]; }
        S1[k * TROWS + r] = v;
    }
    __syncthreads();

    mlp_layer2<64, 64, true >(S1, S2,  0,     131072);
    mlp_layer2<64, 64, true >(S2, S1,  8192,  131200);
    mlp_layer2<64, 64, false>(S1, S2,  16384, 131328);   // hand out -> S2 rows [0,64)

    // ---- gather board input (80 feats) into S1 [k][row] ----
    for (int i = t; i < 80 * TROWS; i += NTHREADS) {
        int r = i & 63, k = i >> 6;
        int c = k >> 4, w = k & 15;
        float v;
        if (w < 8) { int s  = (int)Ss[r * 52 + 9 + 2 * c]; v = blob[0  + s * 8 + w]; }
        else       { int rk = (int)Ss[r * 52 + 8 + 2 * c]; v = blob[40 + rk * 8 + (w - 8)]; }
        S1[k * TROWS + r] = v;
    }
    __syncthreads();

    mlp_layer2<80, 80, true >(S1, S2 + 64 * TROWS, 24576, 131456);
    mlp_layer2<80, 80, true >(S2 + 64 * TROWS, S1, 37376, 131616);
    mlp_layer2<80, 80, false>(S1, S2 + 64 * TROWS, 50176, 131776); // board -> S2 rows [64,144)

    // ---- combined MLP: S2 = [hand(64); board(80)] ----
    mlp_layer2<144, 144, true>(S2, S1, 62976,  131936);
    mlp_layer2<144, 64,  true>(S1, S2, 104448, 132224);
    mlp_final2(S2, out, g0, 122880, 132352);
}

extern "C" void kernel_launch(void* const* d_in, const int* in_sizes, int n_in,
                              void* d_out, int out_size)
{
    (void)n_in; (void)out_size;
    cudaFuncSetAttribute(preproc_kernel, cudaFuncAttributeMaxDynamicSharedMemorySize, SMEM_BYTES);

    // duplicate weights+biases into packed-pair scratch (graph-capturable, ~2us)
    dup_kernel<<<(66240 + 255) / 256, 256>>>(
        (const float*)d_in[3],  (const float*)d_in[5],  (const float*)d_in[7],
        (const float*)d_in[9],  (const float*)d_in[11], (const float*)d_in[13],
        (const float*)d_in[15], (const float*)d_in[17], (const float*)d_in[19],
        (const float*)d_in[4],  (const float*)d_in[6],  (const float*)d_in[8],
        (const float*)d_in[10], (const float*)d_in[12], (const float*)d_in[14],
        (const float*)d_in[16], (const float*)d_in[18], (const float*)d_in[20]);

    const int nrows = in_sizes[0] / 50;     // 262144
    const int grid  = nrows / TROWS;        // 4096

    preproc_kernel<<<grid, NTHREADS, SMEM_BYTES>>>(
        (const float*)d_in[0],
        (const float*)d_in[1],  (const float*)d_in[2],
        (const float*)d_in[21], (const float*)d_in[22],
        (const float*)d_in[23], (const float*)d_in[24],
        (const float*)d_in[25], (const float*)d_in[26],
        (const float*)d_in[27], (const float*)d_in[28],
        (float*)d_out);
}